// round 13
// baseline (speedup 1.0000x reference)
#include <cuda_runtime.h>
#include <cuda_bf16.h>
#include <math.h>
#include <stdint.h>

#define NHEADS 4
#define HD 64
#define NQ 256
#define KDIM 128

#define SQROW 68          /* V1 / combined rows, f32, natural layout   */
#define KROWP 36          /* K rows: 32 bf16x2 words + pad             */
#define VROWP 68          /* V key-pair rows: 64 bf16x2 words + pad    */
#define WROWP 68          /* W k-pair rows: 64 bf16x2 words + pad      */

#define SQO  0                         /* 256*68  = 17408 */
#define SKO  17408                     /* 272*36  =  9792 */
#define SVO  27200                     /* 136*68  =  9248 */
#define SW1O 36448                     /* 64*68   =  4352 */
#define SW2O 40800                     /* 64*68   =  4352 */
#define SMEMF 45152                    /* words -> 180608 B */

__device__ float g_maxpool[32*NHEADS*HD];
__device__ float g_h1[32*512];

__device__ __forceinline__ float gelu_exact(float x){
    return 0.5f*x*(1.0f+erff(x*0.70710678118654752440f));
}
// pack two f32 -> bf16x2 word; e0 -> low half (lower k/col index)
__device__ __forceinline__ uint32_t bf2(float e0, float e1){
    uint32_t r; asm("cvt.rn.bf16x2.f32 %0, %1, %2;" : "=r"(r) : "f"(e1), "f"(e0)); return r;
}
__device__ __forceinline__ float2 bf2f(uint32_t w){
    __nv_bfloat162 h = *reinterpret_cast<__nv_bfloat162*>(&w);
    return __bfloat1622float2(h);           // .x = low half
}
__device__ __forceinline__ void mma16(float d[4], const uint32_t a[4], const uint32_t b[2]){
    asm volatile("mma.sync.aligned.m16n8k16.row.col.f32.bf16.bf16.f32 "
        "{%0,%1,%2,%3},{%4,%5,%6,%7},{%8,%9},{%0,%1,%2,%3};\n"
        : "+f"(d[0]),"+f"(d[1]),"+f"(d[2]),"+f"(d[3])
        : "r"(a[0]),"r"(a[1]),"r"(a[2]),"r"(a[3]),"r"(b[0]),"r"(b[1]));
}
// 8x8 block transpose for col packing: col -> (col%8)*8 + col/8
__device__ __forceinline__ int vpack(int col){ return (col & 7) * 8 + (col >> 3); }

// ---------------------------------------------------------------------------
// 512 threads / 16 warps; warp owns ONE 16-query m-tile.
// bf16 m16n8k16; K/V/W in smem as packed bf16x2, XOR-swizzled.
// Mainloop software-pipelined 2 chunks deep.
// ---------------------------------------------------------------------------
__global__ __launch_bounds__(512,1)
void attn_mma_kernel(const float* __restrict__ seq, const float* __restrict__ node1,
    const float* __restrict__ node2,
    const float* __restrict__ Wq, const float* __restrict__ bq,
    const float* __restrict__ Wk, const float* __restrict__ bk,
    const float* __restrict__ Wv, const float* __restrict__ bv)
{
    extern __shared__ float sm[];
    uint32_t* smu = (uint32_t*)sm;
    const int h=blockIdx.x, b=blockIdx.y, t=threadIdx.x;
    const int lane=t&31, wid=t>>5, g=lane>>2, t4=lane&3;
    const int stripe=wid*16;
    const float* n1b = node1 + (size_t)b*KDIM*256;
    const float* n2b = node2 + (size_t)b*KDIM*256;
    const float* pooled = seq + (size_t)b*4096*768;

    // zero pads: K rows 257..271, V kp rows 129..135
    for (int i=t; i<15*KROWP; i+=512) smu[SKO + 257*KROWP + i] = 0u;
    for (int i=t; i<7*VROWP;  i+=512) smu[SVO + 129*VROWP + i] = 0u;
    // stage Wv->SW1, Wk->SW2 as bf16x2 k-pair words, col-blocked + swizzled
    for (int i=t; i<64*64; i+=512){
        int kp=i>>6, o=i&63;
        int pos = vpack(o) ^ ((kp&3)<<3);
        smu[SW1O + kp*WROWP + pos] = bf2(Wv[(2*kp)*256+h*HD+o], Wv[(2*kp+1)*256+h*HD+o]);
        smu[SW2O + kp*WROWP + pos] = bf2(Wk[(2*kp)*256+h*HD+o], Wk[(2*kp+1)*256+h*HD+o]);
    }
    __syncthreads();

    // ======== Phase 1: gelu(n2@Wv)->SV(packed), n2@Wk->SK(packed) ========
    {
        float cV[8][4], cK[8][4];
        #pragma unroll
        for (int nt=0; nt<8; nt++){
            float bvx=bv[h*HD+nt*8+2*t4], bvy=bv[h*HD+nt*8+2*t4+1];
            float bkx=bk[h*HD+nt*8+2*t4], bky=bk[h*HD+nt*8+2*t4+1];
            cV[nt][0]=bvx; cV[nt][1]=bvy; cV[nt][2]=bvx; cV[nt][3]=bvy;
            cK[nt][0]=bkx; cK[nt][1]=bky; cK[nt][2]=bkx; cK[nt][3]=bky;
        }
        #pragma unroll 2
        for (int kt=0; kt<8; kt++){
            uint32_t a[4];
            int k0=kt*16+2*t4, r=stripe+g;
            a[0]=bf2(n2b[k0*256+r],        n2b[(k0+1)*256+r]);
            a[1]=bf2(n2b[k0*256+r+8],      n2b[(k0+1)*256+r+8]);
            a[2]=bf2(n2b[(k0+8)*256+r],    n2b[(k0+9)*256+r]);
            a[3]=bf2(n2b[(k0+8)*256+r+8],  n2b[(k0+9)*256+r+8]);
            uint32_t wv0[8], wv1[8], wk0[8], wk1[8];
            {
                int oc=(g^t4)<<3;
                int rA=(8*kt+t4)*WROWP+oc, rB=(8*kt+t4+4)*WROWP+oc;
                *(uint4*)&wv0[0]=*(uint4*)&smu[SW1O+rA]; *(uint4*)&wv0[4]=*(uint4*)&smu[SW1O+rA+4];
                *(uint4*)&wv1[0]=*(uint4*)&smu[SW1O+rB]; *(uint4*)&wv1[4]=*(uint4*)&smu[SW1O+rB+4];
                *(uint4*)&wk0[0]=*(uint4*)&smu[SW2O+rA]; *(uint4*)&wk0[4]=*(uint4*)&smu[SW2O+rA+4];
                *(uint4*)&wk1[0]=*(uint4*)&smu[SW2O+rB]; *(uint4*)&wk1[4]=*(uint4*)&smu[SW2O+rB+4];
            }
            #pragma unroll
            for (int nt=0; nt<8; nt++){
                uint32_t bV[2]={wv0[nt],wv1[nt]};
                uint32_t bK2[2]={wk0[nt],wk1[nt]};
                mma16(cV[nt],a,bV);
                mma16(cK[nt],a,bK2);
            }
        }
        // write K (own-lane packing) and V (key-pair packing via lane pairing)
        {
            int r0=stripe+g, r1=r0+8;
            int kox=((t4^(g&3))<<3);          // r0&3 == r1&3 == g&3
            #pragma unroll
            for (int nt=0; nt<8; nt++){
                smu[SKO + r0*KROWP + kox + nt] = bf2(cK[nt][0], cK[nt][1]);
                smu[SKO + r1*KROWP + kox + nt] = bf2(cK[nt][2], cK[nt][3]);
                float gv0=gelu_exact(cV[nt][0]), gv1=gelu_exact(cV[nt][1]);
                float gv2=gelu_exact(cV[nt][2]), gv3=gelu_exact(cV[nt][3]);
                float pg0=__shfl_xor_sync(~0u,gv0,4), pg1=__shfl_xor_sync(~0u,gv1,4);
                float pg2=__shfl_xor_sync(~0u,gv2,4), pg3=__shfl_xor_sync(~0u,gv3,4);
                if (!(g&1)){
                    int kp0=r0>>1, kp1=r1>>1;
                    int c0=nt*8+2*t4;
                    smu[SVO + kp0*VROWP + (vpack(c0)   ^ ((kp0&3)<<3))] = bf2(gv0,pg0);
                    smu[SVO + kp0*VROWP + (vpack(c0+1) ^ ((kp0&3)<<3))] = bf2(gv1,pg1);
                    smu[SVO + kp1*VROWP + (vpack(c0)   ^ ((kp1&3)<<3))] = bf2(gv2,pg2);
                    smu[SVO + kp1*VROWP + (vpack(c0+1) ^ ((kp1&3)<<3))] = bf2(gv3,pg3);
                }
            }
        }
    }
    // pooled row 256 (scalar over packed bf16 weights)
    if (t < 32){   // K row 256: cols 2t, 2t+1
        float a0=bk[h*HD+2*t], a1=bk[h*HD+2*t+1];
        #pragma unroll 4
        for (int kp=0; kp<64; kp++){
            int sw=(kp&3)<<3;
            float2 f0=bf2f(smu[SW2O + kp*WROWP + (vpack(2*t)^sw)]);
            float2 f1=bf2f(smu[SW2O + kp*WROWP + (vpack(2*t+1)^sw)]);
            float p0=pooled[2*kp], p1=pooled[2*kp+1];
            a0 = fmaf(p0,f0.x,fmaf(p1,f0.y,a0));
            a1 = fmaf(p0,f1.x,fmaf(p1,f1.y,a1));
        }
        smu[SKO + 256*KROWP + ((t&3)<<3) + (t>>2)] = bf2(a0, a1);   // 256&3==0: no swizzle
    }
    if (t >= 64 && t < 64+HD){   // V row 256 (pairs with zero row 257)
        int o=t-64;
        float av=bv[h*HD+o];
        #pragma unroll 4
        for (int kp=0; kp<64; kp++){
            float2 f=bf2f(smu[SW1O + kp*WROWP + (vpack(o)^((kp&3)<<3))]);
            av = fmaf(pooled[2*kp],f.x,fmaf(pooled[2*kp+1],f.y,av));
        }
        smu[SVO + 128*VROWP + vpack(o)] = bf2(gelu_exact(av), 0.f); // 128&3==0
    }
    __syncthreads();
    // stage Wq -> SW2
    for (int i=t; i<64*64; i+=512){
        int kp=i>>6, o=i&63;
        smu[SW2O + kp*WROWP + (vpack(o)^((kp&3)<<3))] =
            bf2(Wq[(2*kp)*256+h*HD+o], Wq[(2*kp+1)*256+h*HD+o]);
    }
    __syncthreads();

    // ======== Phase 2: V1=gelu(n1@Wv)->SQ (f32); Q->bf16 A-frags ========
    uint32_t qa[4][4];
    {
        float cV1[8][4], cQ[8][4];
        #pragma unroll
        for (int nt=0; nt<8; nt++){
            float bvx=bv[h*HD+nt*8+2*t4], bvy=bv[h*HD+nt*8+2*t4+1];
            float bqx=bq[h*HD+nt*8+2*t4], bqy=bq[h*HD+nt*8+2*t4+1];
            cV1[nt][0]=bvx; cV1[nt][1]=bvy; cV1[nt][2]=bvx; cV1[nt][3]=bvy;
            cQ[nt][0]=bqx;  cQ[nt][1]=bqy;  cQ[nt][2]=bqx;  cQ[nt][3]=bqy;
        }
        #pragma unroll 2
        for (int kt=0; kt<8; kt++){
            uint32_t a[4];
            int k0=kt*16+2*t4, r=stripe+g;
            a[0]=bf2(n1b[k0*256+r],       n1b[(k0+1)*256+r]);
            a[1]=bf2(n1b[k0*256+r+8],     n1b[(k0+1)*256+r+8]);
            a[2]=bf2(n1b[(k0+8)*256+r],   n1b[(k0+9)*256+r]);
            a[3]=bf2(n1b[(k0+8)*256+r+8], n1b[(k0+9)*256+r+8]);
            uint32_t wv0[8], wv1[8], wq0[8], wq1[8];
            {
                int oc=(g^t4)<<3;
                int rA=(8*kt+t4)*WROWP+oc, rB=(8*kt+t4+4)*WROWP+oc;
                *(uint4*)&wv0[0]=*(uint4*)&smu[SW1O+rA]; *(uint4*)&wv0[4]=*(uint4*)&smu[SW1O+rA+4];
                *(uint4*)&wv1[0]=*(uint4*)&smu[SW1O+rB]; *(uint4*)&wv1[4]=*(uint4*)&smu[SW1O+rB+4];
                *(uint4*)&wq0[0]=*(uint4*)&smu[SW2O+rA]; *(uint4*)&wq0[4]=*(uint4*)&smu[SW2O+rA+4];
                *(uint4*)&wq1[0]=*(uint4*)&smu[SW2O+rB]; *(uint4*)&wq1[4]=*(uint4*)&smu[SW2O+rB+4];
            }
            #pragma unroll
            for (int nt=0; nt<8; nt++){
                uint32_t bV[2]={wv0[nt],wv1[nt]};
                uint32_t bQ2[2]={wq0[nt],wq1[nt]};
                mma16(cV1[nt],a,bV);
                mma16(cQ[nt],a,bQ2);
            }
        }
        {
            int r0=stripe+g, r1=r0+8;
            #pragma unroll
            for (int nt=0; nt<8; nt++){
                int c=nt*8+2*t4;
                *(float2*)&sm[SQO+r0*SQROW+c]=make_float2(gelu_exact(cV1[nt][0]),gelu_exact(cV1[nt][1]));
                *(float2*)&sm[SQO+r1*SQROW+c]=make_float2(gelu_exact(cV1[nt][2]),gelu_exact(cV1[nt][3]));
            }
            #pragma unroll
            for (int kg=0; kg<4; kg++){
                qa[kg][0]=bf2(0.125f*cQ[2*kg][0],   0.125f*cQ[2*kg][1]);
                qa[kg][1]=bf2(0.125f*cQ[2*kg][2],   0.125f*cQ[2*kg][3]);
                qa[kg][2]=bf2(0.125f*cQ[2*kg+1][0], 0.125f*cQ[2*kg+1][1]);
                qa[kg][3]=bf2(0.125f*cQ[2*kg+1][2], 0.125f*cQ[2*kg+1][3]);
            }
        }
    }

    // ======== Mainloop: chunks 0..15 pipelined in pairs; chunk 16 tail ======
    float ctx[8][4];
    #pragma unroll
    for (int ov=0;ov<8;ov++) for (int e=0;e<4;e++) ctx[ov][e]=0.f;
    float lac[2] = {0.f,0.f};
    const int kox=(t4^(g&3))<<3;
    const int voc=(g^t4)<<3;

    for (int jc2=0; jc2<8; jc2++){
        const int jA=2*jc2, jB=jA+1;
        // ---- K loads for both chunks (issued up front for MLP) ----
        uint32_t kwA[2][8], kwB[2][8];
        #pragma unroll
        for (int nt=0; nt<2; nt++){
            int kbA=SKO + (jA*16+nt*8+g)*KROWP + kox;
            int kbB=SKO + (jB*16+nt*8+g)*KROWP + kox;
            *(uint4*)&kwA[nt][0]=*(uint4*)&smu[kbA];
            *(uint4*)&kwA[nt][4]=*(uint4*)&smu[kbA+4];
            *(uint4*)&kwB[nt][0]=*(uint4*)&smu[kbB];
            *(uint4*)&kwB[nt][4]=*(uint4*)&smu[kbB+4];
        }
        // ---- QK A ----
        float sA[2][4];
        #pragma unroll
        for (int nt=0;nt<2;nt++) for (int e=0;e<4;e++) sA[nt][e]=0.f;
        #pragma unroll
        for (int nt=0; nt<2; nt++)
            #pragma unroll
            for (int kg=0; kg<4; kg++){
                uint32_t bK[2]={kwA[nt][2*kg],kwA[nt][2*kg+1]};
                mma16(sA[nt], qa[kg], bK);
            }
        // ---- QK B (independent; overlaps exp A) ----
        float sB[2][4];
        #pragma unroll
        for (int nt=0;nt<2;nt++) for (int e=0;e<4;e++) sB[nt][e]=0.f;
        #pragma unroll
        for (int nt=0; nt<2; nt++)
            #pragma unroll
            for (int kg=0; kg<4; kg++){
                uint32_t bK[2]={kwB[nt][2*kg],kwB[nt][2*kg+1]};
                mma16(sB[nt], qa[kg], bK);
            }
        // ---- exp + pack + PV for A ----
        {
            uint32_t va[8], vb[8];
            int bA=SVO + (8*jA+t4)*VROWP + voc;
            int bB=SVO + (8*jA+t4+4)*VROWP + voc;
            *(uint4*)&va[0]=*(uint4*)&smu[bA]; *(uint4*)&va[4]=*(uint4*)&smu[bA+4];
            *(uint4*)&vb[0]=*(uint4*)&smu[bB]; *(uint4*)&vb[4]=*(uint4*)&smu[bB+4];
            float p00=__expf(sA[0][0]), p01=__expf(sA[0][1]);
            float p02=__expf(sA[0][2]), p03=__expf(sA[0][3]);
            float p10=__expf(sA[1][0]), p11=__expf(sA[1][1]);
            float p12=__expf(sA[1][2]), p13=__expf(sA[1][3]);
            lac[0] += (p00+p01)+(p10+p11);
            lac[1] += (p02+p03)+(p12+p13);
            uint32_t pa[4];
            pa[0]=bf2(p00,p01); pa[1]=bf2(p02,p03);
            pa[2]=bf2(p10,p11); pa[3]=bf2(p12,p13);
            #pragma unroll
            for (int ov=0; ov<8; ov++){
                uint32_t bV[2]={va[ov],vb[ov]};
                mma16(ctx[ov], pa, bV);
            }
        }
        // ---- exp + pack + PV for B ----
        {
            uint32_t va[8], vb[8];
            int bA=SVO + (8*jB+t4)*VROWP + voc;
            int bB=SVO + (8*jB+t4+4)*VROWP + voc;
            *(uint4*)&va[0]=*(uint4*)&smu[bA]; *(uint4*)&va[4]=*(uint4*)&smu[bA+4];
            *(uint4*)&vb[0]=*(uint4*)&smu[bB]; *(uint4*)&vb[4]=*(uint4*)&smu[bB+4];
            float p00=__expf(sB[0][0]), p01=__expf(sB[0][1]);
            float p02=__expf(sB[0][2]), p03=__expf(sB[0][3]);
            float p10=__expf(sB[1][0]), p11=__expf(sB[1][1]);
            float p12=__expf(sB[1][2]), p13=__expf(sB[1][3]);
            lac[0] += (p00+p01)+(p10+p11);
            lac[1] += (p02+p03)+(p12+p13);
            uint32_t pa[4];
            pa[0]=bf2(p00,p01); pa[1]=bf2(p02,p03);
            pa[2]=bf2(p10,p11); pa[3]=bf2(p12,p13);
            #pragma unroll
            for (int ov=0; ov<8; ov++){
                uint32_t bV[2]={va[ov],vb[ov]};
                mma16(ctx[ov], pa, bV);
            }
        }
    }
    // ---- tail: chunk 16 (only key 256 valid) ----
    {
        const int jc=16;
        float s[2][4];
        #pragma unroll
        for (int nt=0;nt<2;nt++) for (int e=0;e<4;e++) s[nt][e]=0.f;
        #pragma unroll
        for (int nt=0; nt<2; nt++){
            int kb=SKO + (jc*16+nt*8+g)*KROWP + kox;
            uint32_t kw[8];
            *(uint4*)&kw[0]=*(uint4*)&smu[kb];
            *(uint4*)&kw[4]=*(uint4*)&smu[kb+4];
            #pragma unroll
            for (int kg=0; kg<4; kg++){
                uint32_t bK[2]={kw[2*kg],kw[2*kg+1]};
                mma16(s[nt], qa[kg], bK);
            }
        }
        float m0=(t4==0)?1.f:0.f;
        float p0=__expf(s[0][0])*m0;
        float p2=__expf(s[0][2])*m0;
        lac[0] += p0;
        lac[1] += p2;
        uint32_t pa[4];
        pa[0]=bf2(p0,0.f); pa[1]=bf2(p2,0.f);
        pa[2]=0u; pa[3]=0u;
        uint32_t va[8], vb[8];
        int bA=SVO + (8*jc+t4)*VROWP + voc;
        int bB=SVO + (8*jc+t4+4)*VROWP + voc;
        *(uint4*)&va[0]=*(uint4*)&smu[bA]; *(uint4*)&va[4]=*(uint4*)&smu[bA+4];
        *(uint4*)&vb[0]=*(uint4*)&smu[bB]; *(uint4*)&vb[4]=*(uint4*)&smu[bB+4];
        #pragma unroll
        for (int ov=0; ov<8; ov++){
            uint32_t bV[2]={va[ov],vb[ov]};
            mma16(ctx[ov], pa, bV);
        }
    }
    #pragma unroll
    for (int rh=0; rh<2; rh++){
        float v=lac[rh];
        v += __shfl_xor_sync(~0u, v, 1);
        v += __shfl_xor_sync(~0u, v, 2);
        lac[rh]=1.f/v;
    }

    // ======== Combine ctx/l + gelu(V1) in place (SQ) ========
    {
        int r0=stripe+g, r1=r0+8;
        float i0=lac[0], i1=lac[1];
        #pragma unroll
        for (int nt=0; nt<8; nt++){
            int c=nt*8+2*t4;
            float2 v0=*(float2*)&sm[SQO+r0*SQROW+c];
            float2 v1=*(float2*)&sm[SQO+r1*SQROW+c];
            *(float2*)&sm[SQO+r0*SQROW+c]=make_float2(fmaf(ctx[nt][0],i0,v0.x),
                                                      fmaf(ctx[nt][1],i0,v0.y));
            *(float2*)&sm[SQO+r1*SQROW+c]=make_float2(fmaf(ctx[nt][2],i1,v1.x),
                                                      fmaf(ctx[nt][3],i1,v1.y));
        }
    }
    __syncthreads();

    // ======== Max over 256 rows -> g_maxpool (8-way split over 512 thr) =====
    {
        int o=t&63, seg=t>>6;
        float mx=-1e30f;
        #pragma unroll 8
        for (int n=seg*32; n<seg*32+32; n++) mx=fmaxf(mx, sm[SQO+n*SQROW+o]);
        sm[SKO + seg*64+o]=mx;
    }
    __syncthreads();
    if (t < HD){
        float mx=-1e30f;
        #pragma unroll
        for (int s8=0; s8<8; s8++) mx=fmaxf(mx, sm[SKO+s8*64+t]);
        g_maxpool[(b*NHEADS+h)*HD+t]=mx;
    }
}

// ---------------------------------------------------------------------------
__device__ __forceinline__ float block_sum(float v, float* red, int t){
    __syncthreads();
    #pragma unroll
    for (int off=16; off; off>>=1) v += __shfl_xor_sync(0xffffffffu, v, off);
    if ((t&31)==0) red[t>>5]=v;
    __syncthreads();
    if (t<8){
        v=red[t];
        #pragma unroll
        for (int off=4; off; off>>=1) v += __shfl_xor_sync(0xffu, v, off);
        if (t==0) red[0]=v;
    }
    __syncthreads();
    return red[0];
}

__global__ __launch_bounds__(256)
void emb_ln_fc1_kernel(const float* __restrict__ seq,
    const float* __restrict__ Wo, const float* __restrict__ bo,
    const float* __restrict__ ln_g, const float* __restrict__ ln_b,
    const float* __restrict__ fc1_w, const float* __restrict__ fc1_b)
{
    __shared__ float mp_s[256];
    __shared__ float emb[832];
    __shared__ float red[32];
    __shared__ float wo_part[4][64];
    __shared__ float part[8][32];
    const int tile=blockIdx.x, b=blockIdx.y, t=threadIdx.x;

    mp_s[t]=g_maxpool[b*256+t];
    for (int i=t;i<768;i+=256) emb[i]=seq[(size_t)b*4096*768+i];
    __syncthreads();
    {
        int o=t&63, seg=t>>6;
        float a=0.f;
        #pragma unroll 8
        for (int k=seg*64;k<seg*64+64;k++) a=fmaf(mp_s[k],Wo[k*64+o],a);
        wo_part[seg][o]=a;
    }
    __syncthreads();
    if (t<64) emb[768+t]=wo_part[0][t]+wo_part[1][t]+wo_part[2][t]+wo_part[3][t]+bo[t];
    __syncthreads();
    float s=0.f;
    for (int i=t;i<832;i+=256) s+=emb[i];
    float mu=block_sum(s,red,t)*(1.0f/832.0f);
    float vs=0.f;
    for (int i=t;i<832;i+=256){ float d=emb[i]-mu; vs+=d*d; }
    float var=block_sum(vs,red,t)*(1.0f/832.0f);
    float inv_std=rsqrtf(var+1e-5f);
    for (int i=t;i<832;i+=256) emb[i]=(emb[i]-mu)*inv_std*ln_g[i]+ln_b[i];
    __syncthreads();
    {
        const int col=t&31, seg=t>>5, gcol=tile*32+col;
        const float* w=fc1_w+gcol;
        float a=0.f;
        const int k0=seg*104;
        #pragma unroll 8
        for (int k=k0;k<k0+104;k++) a=fmaf(emb[k],w[(size_t)k*512],a);
        part[seg][col]=a;
    }
    __syncthreads();
    if (t<32){
        float sum=part[0][t]+part[1][t]+part[2][t]+part[3][t]
                 +part[4][t]+part[5][t]+part[6][t]+part[7][t];
        int gc=tile*32+t;
        g_h1[b*512+gc]=gelu_exact(sum+fc1_b[gc]);
    }
}

__global__ __launch_bounds__(512)
void fc2_fc3_kernel(const float* __restrict__ fc2_w, const float* __restrict__ fc2_b,
                    const float* __restrict__ fc3_w, const float* __restrict__ fc3_b,
                    float* __restrict__ out)
{
    __shared__ float hs[512];
    __shared__ float part[2][200];
    __shared__ float h2[200];
    const int b=blockIdx.x, t=threadIdx.x;

    hs[t]=g_h1[b*512+t];
    __syncthreads();
    {
        int seg=t>>8, o=t&255;
        if (o<200){
            const float* w=fc2_w+(size_t)(seg*256)*200+o;
            const float* x=hs+seg*256;
            float a0=0.f, a1=0.f;
            #pragma unroll 8
            for (int k=0;k<256;k+=2){
                a0=fmaf(x[k],  w[(size_t)k*200],     a0);
                a1=fmaf(x[k+1],w[(size_t)(k+1)*200], a1);
            }
            part[seg][o]=a0+a1;
        }
    }
    __syncthreads();
    if (t<200) h2[t]=gelu_exact(part[0][t]+part[1][t]+fc2_b[t]);
    __syncthreads();
    if (t<64){
        int o=t>>5, lane=t&31;
        float a=0.f;
        #pragma unroll
        for (int k=lane;k<200;k+=32) a=fmaf(h2[k],fc3_w[k*2+o],a);
        #pragma unroll
        for (int off=16;off;off>>=1) a+=__shfl_xor_sync(0xffffffffu,a,off);
        if (lane==0) out[b*2+o]=a+fc3_b[o];
    }
}

// ---------------------------------------------------------------------------
extern "C" void kernel_launch(void* const* d_in, const int* in_sizes, int n_in,
                              void* d_out, int out_size)
{
    const float* seq   =(const float*)d_in[0];
    const float* node1 =(const float*)d_in[1];
    const float* node2 =(const float*)d_in[2];
    const float* Wq    =(const float*)d_in[3];
    const float* bq    =(const float*)d_in[4];
    const float* Wk    =(const float*)d_in[5];
    const float* bk    =(const float*)d_in[6];
    const float* Wv    =(const float*)d_in[7];
    const float* bv    =(const float*)d_in[8];
    const float* Wo    =(const float*)d_in[9];
    const float* bo    =(const float*)d_in[10];
    const float* ln_g  =(const float*)d_in[11];
    const float* ln_b  =(const float*)d_in[12];
    const float* fc1_w =(const float*)d_in[13];
    const float* fc1_b =(const float*)d_in[14];
    const float* fc2_w =(const float*)d_in[15];
    const float* fc2_b =(const float*)d_in[16];
    const float* fc3_w =(const float*)d_in[17];
    const float* fc3_b =(const float*)d_in[18];

    const size_t smem_bytes = (size_t)SMEMF * sizeof(float);
    cudaFuncSetAttribute(attn_mma_kernel,
                         cudaFuncAttributeMaxDynamicSharedMemorySize, (int)smem_bytes);

    attn_mma_kernel<<<dim3(NHEADS,32), 512, smem_bytes>>>(
        seq, node1, node2, Wq, bq, Wk, bk, Wv, bv);

    emb_ln_fc1_kernel<<<dim3(16,32), 256>>>(seq, Wo, bo, ln_g, ln_b, fc1_w, fc1_b);
    fc2_fc3_kernel<<<32, 512>>>(fc2_w, fc2_b, fc3_w, fc3_b, (float*)d_out);
}

// round 14
// speedup vs baseline: 1.1122x; 1.1122x over previous
#include <cuda_runtime.h>
#include <cuda_bf16.h>
#include <math.h>
#include <stdint.h>

#define NHEADS 4
#define HD 64
#define NQ 256
#define KDIM 128

#define SQROW 68          /* V1 rows, f32, natural layout              */
#define KROWP 36          /* K rows: 32 bf16x2 words + pad             */
#define VROWP 68          /* V key-pair rows: 64 bf16x2 words + pad    */
#define WROWP 68          /* W k-pair rows: 64 bf16x2 words + pad      */

#define SQO  0                         /* 256*68  = 17408 */
#define SKO  17408                     /* 272*36  =  9792 */
#define SVO  27200                     /* 136*68  =  9248 */
#define SW1O 36448                     /* 64*68   =  4352 */
#define SW2O 40800                     /* 64*68   =  4352 */
#define SW3O 45152                     /* 64*68   =  4352 */
#define SMEMF 49504                    /* words -> 198016 B */

__device__ float g_maxpool[32*NHEADS*HD];
__device__ float g_h1[32*512];

__device__ __forceinline__ float gelu_exact(float x){
    return 0.5f*x*(1.0f+erff(x*0.70710678118654752440f));
}
// pack two f32 -> bf16x2 word; e0 -> low half (lower k/col index)
__device__ __forceinline__ uint32_t bf2(float e0, float e1){
    uint32_t r; asm("cvt.rn.bf16x2.f32 %0, %1, %2;" : "=r"(r) : "f"(e1), "f"(e0)); return r;
}
__device__ __forceinline__ float2 bf2f(uint32_t w){
    __nv_bfloat162 h = *reinterpret_cast<__nv_bfloat162*>(&w);
    return __bfloat1622float2(h);           // .x = low half
}
__device__ __forceinline__ void mma16(float d[4], const uint32_t a[4], const uint32_t b[2]){
    asm volatile("mma.sync.aligned.m16n8k16.row.col.f32.bf16.bf16.f32 "
        "{%0,%1,%2,%3},{%4,%5,%6,%7},{%8,%9},{%0,%1,%2,%3};\n"
        : "+f"(d[0]),"+f"(d[1]),"+f"(d[2]),"+f"(d[3])
        : "r"(a[0]),"r"(a[1]),"r"(a[2]),"r"(a[3]),"r"(b[0]),"r"(b[1]));
}
// 8x8 block transpose for col packing: col -> (col%8)*8 + col/8
__device__ __forceinline__ int vpack(int col){ return (col & 7) * 8 + (col >> 3); }

// ---------------------------------------------------------------------------
// 256 threads / 8 warps; warp owns 32 queries (2 x 16-row m-tiles).
// bf16 m16n8k16; K/V/W in smem as packed bf16x2, XOR-swizzled.
// All 3 weights pre-staged; register max-pool epilogue (combined matrix
// never materialized — reference only max-pools it).
// ---------------------------------------------------------------------------
__global__ __launch_bounds__(256,1)
void attn_mma_kernel(const float* __restrict__ seq, const float* __restrict__ node1,
    const float* __restrict__ node2,
    const float* __restrict__ Wq, const float* __restrict__ bq,
    const float* __restrict__ Wk, const float* __restrict__ bk,
    const float* __restrict__ Wv, const float* __restrict__ bv)
{
    extern __shared__ float sm[];
    uint32_t* smu = (uint32_t*)sm;
    const int h=blockIdx.x, b=blockIdx.y, t=threadIdx.x;
    const int lane=t&31, wid=t>>5, g=lane>>2, t4=lane&3;
    const int stripe=wid*32;
    const float* n1b = node1 + (size_t)b*KDIM*256;
    const float* n2b = node2 + (size_t)b*KDIM*256;
    const float* pooled = seq + (size_t)b*4096*768;

    // zero pads: K rows 257..271, V kp rows 129..135
    for (int i=t; i<15*KROWP; i+=256) smu[SKO + 257*KROWP + i] = 0u;
    for (int i=t; i<7*VROWP;  i+=256) smu[SVO + 129*VROWP + i] = 0u;
    // stage Wv->SW1, Wk->SW2, Wq->SW3 (bf16x2 k-pair words, packed+swizzled)
    for (int i=t; i<64*64; i+=256){
        int kp=i>>6, o=i&63;
        int pos = vpack(o) ^ ((kp&3)<<3);
        smu[SW1O + kp*WROWP + pos] = bf2(Wv[(2*kp)*256+h*HD+o], Wv[(2*kp+1)*256+h*HD+o]);
        smu[SW2O + kp*WROWP + pos] = bf2(Wk[(2*kp)*256+h*HD+o], Wk[(2*kp+1)*256+h*HD+o]);
        smu[SW3O + kp*WROWP + pos] = bf2(Wq[(2*kp)*256+h*HD+o], Wq[(2*kp+1)*256+h*HD+o]);
    }
    __syncthreads();

    // ======== Phase 1: gelu(n2@Wv)->SV(packed), n2@Wk->SK(packed) ========
    {
        float cV[2][8][4], cK[2][8][4];
        #pragma unroll
        for (int nt=0; nt<8; nt++){
            float bvx=bv[h*HD+nt*8+2*t4], bvy=bv[h*HD+nt*8+2*t4+1];
            float bkx=bk[h*HD+nt*8+2*t4], bky=bk[h*HD+nt*8+2*t4+1];
            #pragma unroll
            for (int mt=0; mt<2; mt++){
                cV[mt][nt][0]=bvx; cV[mt][nt][1]=bvy; cV[mt][nt][2]=bvx; cV[mt][nt][3]=bvy;
                cK[mt][nt][0]=bkx; cK[mt][nt][1]=bky; cK[mt][nt][2]=bkx; cK[mt][nt][3]=bky;
            }
        }
        #pragma unroll 2
        for (int kt=0; kt<8; kt++){
            uint32_t a[2][4];
            int k0=kt*16+2*t4;
            #pragma unroll
            for (int mt=0; mt<2; mt++){
                int r=stripe+mt*16+g;
                a[mt][0]=bf2(n2b[k0*256+r],        n2b[(k0+1)*256+r]);
                a[mt][1]=bf2(n2b[k0*256+r+8],      n2b[(k0+1)*256+r+8]);
                a[mt][2]=bf2(n2b[(k0+8)*256+r],    n2b[(k0+9)*256+r]);
                a[mt][3]=bf2(n2b[(k0+8)*256+r+8],  n2b[(k0+9)*256+r+8]);
            }
            uint32_t wv0[8], wv1[8], wk0[8], wk1[8];
            {
                int oc=(g^t4)<<3;
                int rA=(8*kt+t4)*WROWP+oc, rB=(8*kt+t4+4)*WROWP+oc;
                *(uint4*)&wv0[0]=*(uint4*)&smu[SW1O+rA]; *(uint4*)&wv0[4]=*(uint4*)&smu[SW1O+rA+4];
                *(uint4*)&wv1[0]=*(uint4*)&smu[SW1O+rB]; *(uint4*)&wv1[4]=*(uint4*)&smu[SW1O+rB+4];
                *(uint4*)&wk0[0]=*(uint4*)&smu[SW2O+rA]; *(uint4*)&wk0[4]=*(uint4*)&smu[SW2O+rA+4];
                *(uint4*)&wk1[0]=*(uint4*)&smu[SW2O+rB]; *(uint4*)&wk1[4]=*(uint4*)&smu[SW2O+rB+4];
            }
            #pragma unroll
            for (int nt=0; nt<8; nt++){
                uint32_t bV[2]={wv0[nt],wv1[nt]};
                uint32_t bK2[2]={wk0[nt],wk1[nt]};
                mma16(cV[0][nt],a[0],bV);  mma16(cV[1][nt],a[1],bV);
                mma16(cK[0][nt],a[0],bK2); mma16(cK[1][nt],a[1],bK2);
            }
        }
        // write K (own-lane packing) and V (key-pair packing via lane pairing)
        #pragma unroll
        for (int mt=0; mt<2; mt++){
            int r0=stripe+mt*16+g, r1=r0+8;
            int kox=((t4^(g&3))<<3);          // r0&3 == r1&3 == g&3
            #pragma unroll
            for (int nt=0; nt<8; nt++){
                smu[SKO + r0*KROWP + kox + nt] = bf2(cK[mt][nt][0], cK[mt][nt][1]);
                smu[SKO + r1*KROWP + kox + nt] = bf2(cK[mt][nt][2], cK[mt][nt][3]);
                float gv0=gelu_exact(cV[mt][nt][0]), gv1=gelu_exact(cV[mt][nt][1]);
                float gv2=gelu_exact(cV[mt][nt][2]), gv3=gelu_exact(cV[mt][nt][3]);
                float pg0=__shfl_xor_sync(~0u,gv0,4), pg1=__shfl_xor_sync(~0u,gv1,4);
                float pg2=__shfl_xor_sync(~0u,gv2,4), pg3=__shfl_xor_sync(~0u,gv3,4);
                if (!(g&1)){
                    int kp0=r0>>1, kp1=r1>>1;
                    int c0=nt*8+2*t4;
                    smu[SVO + kp0*VROWP + (vpack(c0)   ^ ((kp0&3)<<3))] = bf2(gv0,pg0);
                    smu[SVO + kp0*VROWP + (vpack(c0+1) ^ ((kp0&3)<<3))] = bf2(gv1,pg1);
                    smu[SVO + kp1*VROWP + (vpack(c0)   ^ ((kp1&3)<<3))] = bf2(gv2,pg2);
                    smu[SVO + kp1*VROWP + (vpack(c0+1) ^ ((kp1&3)<<3))] = bf2(gv3,pg3);
                }
            }
        }
    }
    // pooled row 256 (scalar over packed bf16 weights)
    if (t < 32){   // K row 256: cols 2t, 2t+1
        float a0=bk[h*HD+2*t], a1=bk[h*HD+2*t+1];
        #pragma unroll 4
        for (int kp=0; kp<64; kp++){
            int sw=(kp&3)<<3;
            float2 f0=bf2f(smu[SW2O + kp*WROWP + (vpack(2*t)^sw)]);
            float2 f1=bf2f(smu[SW2O + kp*WROWP + (vpack(2*t+1)^sw)]);
            float p0=pooled[2*kp], p1=pooled[2*kp+1];
            a0 = fmaf(p0,f0.x,fmaf(p1,f0.y,a0));
            a1 = fmaf(p0,f1.x,fmaf(p1,f1.y,a1));
        }
        smu[SKO + 256*KROWP + ((t&3)<<3) + (t>>2)] = bf2(a0, a1);   // 256&3==0: no swizzle
    }
    if (t < HD){   // V row 256 (pairs with zero row 257)
        float av=bv[h*HD+t];
        #pragma unroll 4
        for (int kp=0; kp<64; kp++){
            float2 f=bf2f(smu[SW1O + kp*WROWP + (vpack(t)^((kp&3)<<3))]);
            av = fmaf(pooled[2*kp],f.x,fmaf(pooled[2*kp+1],f.y,av));
        }
        smu[SVO + 128*VROWP + vpack(t)] = bf2(gelu_exact(av), 0.f); // 128&3==0
    }

    // ======== Phase 2: V1=gelu(n1@Wv)->SQ (f32, own rows); Q->bf16 A-frags ==
    uint32_t qa[2][4][4];
    {
        float cV1[2][8][4], cQ[2][8][4];
        #pragma unroll
        for (int nt=0; nt<8; nt++){
            float bvx=bv[h*HD+nt*8+2*t4], bvy=bv[h*HD+nt*8+2*t4+1];
            float bqx=bq[h*HD+nt*8+2*t4], bqy=bq[h*HD+nt*8+2*t4+1];
            #pragma unroll
            for (int mt=0; mt<2; mt++){
                cV1[mt][nt][0]=bvx; cV1[mt][nt][1]=bvy; cV1[mt][nt][2]=bvx; cV1[mt][nt][3]=bvy;
                cQ[mt][nt][0]=bqx;  cQ[mt][nt][1]=bqy;  cQ[mt][nt][2]=bqx;  cQ[mt][nt][3]=bqy;
            }
        }
        #pragma unroll 2
        for (int kt=0; kt<8; kt++){
            uint32_t a[2][4];
            int k0=kt*16+2*t4;
            #pragma unroll
            for (int mt=0; mt<2; mt++){
                int r=stripe+mt*16+g;
                a[mt][0]=bf2(n1b[k0*256+r],       n1b[(k0+1)*256+r]);
                a[mt][1]=bf2(n1b[k0*256+r+8],     n1b[(k0+1)*256+r+8]);
                a[mt][2]=bf2(n1b[(k0+8)*256+r],   n1b[(k0+9)*256+r]);
                a[mt][3]=bf2(n1b[(k0+8)*256+r+8], n1b[(k0+9)*256+r+8]);
            }
            uint32_t wv0[8], wv1[8], wq0[8], wq1[8];
            {
                int oc=(g^t4)<<3;
                int rA=(8*kt+t4)*WROWP+oc, rB=(8*kt+t4+4)*WROWP+oc;
                *(uint4*)&wv0[0]=*(uint4*)&smu[SW1O+rA]; *(uint4*)&wv0[4]=*(uint4*)&smu[SW1O+rA+4];
                *(uint4*)&wv1[0]=*(uint4*)&smu[SW1O+rB]; *(uint4*)&wv1[4]=*(uint4*)&smu[SW1O+rB+4];
                *(uint4*)&wq0[0]=*(uint4*)&smu[SW3O+rA]; *(uint4*)&wq0[4]=*(uint4*)&smu[SW3O+rA+4];
                *(uint4*)&wq1[0]=*(uint4*)&smu[SW3O+rB]; *(uint4*)&wq1[4]=*(uint4*)&smu[SW3O+rB+4];
            }
            #pragma unroll
            for (int nt=0; nt<8; nt++){
                uint32_t bV[2]={wv0[nt],wv1[nt]};
                uint32_t bQ2[2]={wq0[nt],wq1[nt]};
                mma16(cV1[0][nt],a[0],bV);  mma16(cV1[1][nt],a[1],bV);
                mma16(cQ[0][nt],a[0],bQ2);  mma16(cQ[1][nt],a[1],bQ2);
            }
        }
        #pragma unroll
        for (int mt=0; mt<2; mt++){
            int r0=stripe+mt*16+g, r1=r0+8;
            #pragma unroll
            for (int nt=0; nt<8; nt++){
                int c=nt*8+2*t4;
                *(float2*)&sm[SQO+r0*SQROW+c]=make_float2(gelu_exact(cV1[mt][nt][0]),gelu_exact(cV1[mt][nt][1]));
                *(float2*)&sm[SQO+r1*SQROW+c]=make_float2(gelu_exact(cV1[mt][nt][2]),gelu_exact(cV1[mt][nt][3]));
            }
            #pragma unroll
            for (int kg=0; kg<4; kg++){
                qa[mt][kg][0]=bf2(0.125f*cQ[mt][2*kg][0],   0.125f*cQ[mt][2*kg][1]);
                qa[mt][kg][1]=bf2(0.125f*cQ[mt][2*kg][2],   0.125f*cQ[mt][2*kg][3]);
                qa[mt][kg][2]=bf2(0.125f*cQ[mt][2*kg+1][0], 0.125f*cQ[mt][2*kg+1][1]);
                qa[mt][kg][3]=bf2(0.125f*cQ[mt][2*kg+1][2], 0.125f*cQ[mt][2*kg+1][3]);
            }
        }
    }
    __syncthreads();   // SK/SV complete (all warps + pooled rows) before mainloop

    // ======== Mainloop: chunks 0..15 pipelined in pairs; chunk 16 tail ======
    float ctx[2][8][4];
    #pragma unroll
    for (int mt=0;mt<2;mt++) for (int ov=0;ov<8;ov++) for (int e=0;e<4;e++) ctx[mt][ov][e]=0.f;
    float lac[2][2] = {{0.f,0.f},{0.f,0.f}};
    const int kox=(t4^(g&3))<<3;
    const int voc=(g^t4)<<3;

    for (int jc2=0; jc2<8; jc2++){
        const int jA=2*jc2, jB=jA+1;
        uint32_t kwA[2][8], kwB[2][8];
        #pragma unroll
        for (int nt=0; nt<2; nt++){
            int kbA=SKO + (jA*16+nt*8+g)*KROWP + kox;
            int kbB=SKO + (jB*16+nt*8+g)*KROWP + kox;
            *(uint4*)&kwA[nt][0]=*(uint4*)&smu[kbA];
            *(uint4*)&kwA[nt][4]=*(uint4*)&smu[kbA+4];
            *(uint4*)&kwB[nt][0]=*(uint4*)&smu[kbB];
            *(uint4*)&kwB[nt][4]=*(uint4*)&smu[kbB+4];
        }
        float sA[2][2][4];
        #pragma unroll
        for (int mt=0;mt<2;mt++) for (int nt=0;nt<2;nt++) for (int e=0;e<4;e++) sA[mt][nt][e]=0.f;
        #pragma unroll
        for (int nt=0; nt<2; nt++)
            #pragma unroll
            for (int kg=0; kg<4; kg++){
                uint32_t bK[2]={kwA[nt][2*kg],kwA[nt][2*kg+1]};
                mma16(sA[0][nt], qa[0][kg], bK);
                mma16(sA[1][nt], qa[1][kg], bK);
            }
        float sB[2][2][4];
        #pragma unroll
        for (int mt=0;mt<2;mt++) for (int nt=0;nt<2;nt++) for (int e=0;e<4;e++) sB[mt][nt][e]=0.f;
        #pragma unroll
        for (int nt=0; nt<2; nt++)
            #pragma unroll
            for (int kg=0; kg<4; kg++){
                uint32_t bK[2]={kwB[nt][2*kg],kwB[nt][2*kg+1]};
                mma16(sB[0][nt], qa[0][kg], bK);
                mma16(sB[1][nt], qa[1][kg], bK);
            }
        {
            uint32_t va[8], vb[8];
            int bA=SVO + (8*jA+t4)*VROWP + voc;
            int bB=SVO + (8*jA+t4+4)*VROWP + voc;
            *(uint4*)&va[0]=*(uint4*)&smu[bA]; *(uint4*)&va[4]=*(uint4*)&smu[bA+4];
            *(uint4*)&vb[0]=*(uint4*)&smu[bB]; *(uint4*)&vb[4]=*(uint4*)&smu[bB+4];
            uint32_t pa[2][4];
            #pragma unroll
            for (int mt=0;mt<2;mt++){
                float p00=__expf(sA[mt][0][0]), p01=__expf(sA[mt][0][1]);
                float p02=__expf(sA[mt][0][2]), p03=__expf(sA[mt][0][3]);
                float p10=__expf(sA[mt][1][0]), p11=__expf(sA[mt][1][1]);
                float p12=__expf(sA[mt][1][2]), p13=__expf(sA[mt][1][3]);
                lac[mt][0] += (p00+p01)+(p10+p11);
                lac[mt][1] += (p02+p03)+(p12+p13);
                pa[mt][0]=bf2(p00,p01); pa[mt][1]=bf2(p02,p03);
                pa[mt][2]=bf2(p10,p11); pa[mt][3]=bf2(p12,p13);
            }
            #pragma unroll
            for (int ov=0; ov<8; ov++){
                uint32_t bV[2]={va[ov],vb[ov]};
                mma16(ctx[0][ov], pa[0], bV);
                mma16(ctx[1][ov], pa[1], bV);
            }
        }
        {
            uint32_t va[8], vb[8];
            int bA=SVO + (8*jB+t4)*VROWP + voc;
            int bB=SVO + (8*jB+t4+4)*VROWP + voc;
            *(uint4*)&va[0]=*(uint4*)&smu[bA]; *(uint4*)&va[4]=*(uint4*)&smu[bA+4];
            *(uint4*)&vb[0]=*(uint4*)&smu[bB]; *(uint4*)&vb[4]=*(uint4*)&smu[bB+4];
            uint32_t pa[2][4];
            #pragma unroll
            for (int mt=0;mt<2;mt++){
                float p00=__expf(sB[mt][0][0]), p01=__expf(sB[mt][0][1]);
                float p02=__expf(sB[mt][0][2]), p03=__expf(sB[mt][0][3]);
                float p10=__expf(sB[mt][1][0]), p11=__expf(sB[mt][1][1]);
                float p12=__expf(sB[mt][1][2]), p13=__expf(sB[mt][1][3]);
                lac[mt][0] += (p00+p01)+(p10+p11);
                lac[mt][1] += (p02+p03)+(p12+p13);
                pa[mt][0]=bf2(p00,p01); pa[mt][1]=bf2(p02,p03);
                pa[mt][2]=bf2(p10,p11); pa[mt][3]=bf2(p12,p13);
            }
            #pragma unroll
            for (int ov=0; ov<8; ov++){
                uint32_t bV[2]={va[ov],vb[ov]};
                mma16(ctx[0][ov], pa[0], bV);
                mma16(ctx[1][ov], pa[1], bV);
            }
        }
    }
    // ---- tail: chunk 16 (only key 256 valid) ----
    {
        const int jc=16;
        float s[2][2][4];
        #pragma unroll
        for (int mt=0;mt<2;mt++) for (int nt=0;nt<2;nt++) for (int e=0;e<4;e++) s[mt][nt][e]=0.f;
        #pragma unroll
        for (int nt=0; nt<2; nt++){
            int kb=SKO + (jc*16+nt*8+g)*KROWP + kox;
            uint32_t kw[8];
            *(uint4*)&kw[0]=*(uint4*)&smu[kb];
            *(uint4*)&kw[4]=*(uint4*)&smu[kb+4];
            #pragma unroll
            for (int kg=0; kg<4; kg++){
                uint32_t bK[2]={kw[2*kg],kw[2*kg+1]};
                mma16(s[0][nt], qa[0][kg], bK);
                mma16(s[1][nt], qa[1][kg], bK);
            }
        }
        float m0=(t4==0)?1.f:0.f;
        uint32_t pa[2][4];
        #pragma unroll
        for (int mt=0;mt<2;mt++){
            float p0=__expf(s[mt][0][0])*m0;
            float p2=__expf(s[mt][0][2])*m0;
            lac[mt][0] += p0;
            lac[mt][1] += p2;
            pa[mt][0]=bf2(p0,0.f); pa[mt][1]=bf2(p2,0.f);
            pa[mt][2]=0u; pa[mt][3]=0u;
        }
        uint32_t va[8], vb[8];
        int bA=SVO + (8*jc+t4)*VROWP + voc;
        int bB=SVO + (8*jc+t4+4)*VROWP + voc;
        *(uint4*)&va[0]=*(uint4*)&smu[bA]; *(uint4*)&va[4]=*(uint4*)&smu[bA+4];
        *(uint4*)&vb[0]=*(uint4*)&smu[bB]; *(uint4*)&vb[4]=*(uint4*)&smu[bB+4];
        #pragma unroll
        for (int ov=0; ov<8; ov++){
            uint32_t bV[2]={va[ov],vb[ov]};
            mma16(ctx[0][ov], pa[0], bV);
            mma16(ctx[1][ov], pa[1], bV);
        }
    }
    #pragma unroll
    for (int mt=0;mt<2;mt++) for (int rh=0;rh<2;rh++){
        float v=lac[mt][rh];
        v += __shfl_xor_sync(~0u, v, 1);
        v += __shfl_xor_sync(~0u, v, 2);
        lac[mt][rh]=1.f/v;
    }

    // ======== Register max-pool: max over combined = ctx/l + gelu(V1) ======
    // (combined matrix is ONLY max-pooled by the reference — never stored)
    float mxc[8][2];
    #pragma unroll
    for (int nt=0; nt<8; nt++){
        float m0=-1e30f, m1=-1e30f;
        #pragma unroll
        for (int mt=0; mt<2; mt++){
            int r0=stripe+mt*16+g, r1=r0+8;
            int c=nt*8+2*t4;
            float2 v0=*(float2*)&sm[SQO+r0*SQROW+c];
            float2 v1=*(float2*)&sm[SQO+r1*SQROW+c];
            float i0=lac[mt][0], i1=lac[mt][1];
            m0 = fmaxf(m0, fmaxf(fmaf(ctx[mt][nt][0],i0,v0.x),
                                 fmaf(ctx[mt][nt][2],i1,v1.x)));
            m1 = fmaxf(m1, fmaxf(fmaf(ctx[mt][nt][1],i0,v0.y),
                                 fmaf(ctx[mt][nt][3],i1,v1.y)));
        }
        mxc[nt][0]=m0; mxc[nt][1]=m1;
    }
    #pragma unroll
    for (int nt=0; nt<8; nt++){
        #pragma unroll
        for (int e=0; e<2; e++){
            float m=mxc[nt][e];
            m=fmaxf(m,__shfl_xor_sync(~0u,m,4));
            m=fmaxf(m,__shfl_xor_sync(~0u,m,8));
            m=fmaxf(m,__shfl_xor_sync(~0u,m,16));
            mxc[nt][e]=m;
        }
    }
    __syncthreads();              // all warps done reading SK/SV; reuse SK as scratch
    if (g==0){
        #pragma unroll
        for (int nt=0; nt<8; nt++){
            sm[SKO + wid*64 + nt*8+2*t4]   = mxc[nt][0];
            sm[SKO + wid*64 + nt*8+2*t4+1] = mxc[nt][1];
        }
    }
    __syncthreads();
    if (t < HD){
        float mx=-1e30f;
        #pragma unroll
        for (int w=0; w<8; w++) mx=fmaxf(mx, sm[SKO+w*64+t]);
        g_maxpool[(b*NHEADS+h)*HD+t]=mx;
    }
}

// ---------------------------------------------------------------------------
__device__ __forceinline__ float block_sum(float v, float* red, int t){
    __syncthreads();
    #pragma unroll
    for (int off=16; off; off>>=1) v += __shfl_xor_sync(0xffffffffu, v, off);
    if ((t&31)==0) red[t>>5]=v;
    __syncthreads();
    if (t<8){
        v=red[t];
        #pragma unroll
        for (int off=4; off; off>>=1) v += __shfl_xor_sync(0xffu, v, off);
        if (t==0) red[0]=v;
    }
    __syncthreads();
    return red[0];
}

__global__ __launch_bounds__(256)
void emb_ln_fc1_kernel(const float* __restrict__ seq,
    const float* __restrict__ Wo, const float* __restrict__ bo,
    const float* __restrict__ ln_g, const float* __restrict__ ln_b,
    const float* __restrict__ fc1_w, const float* __restrict__ fc1_b)
{
    __shared__ float mp_s[256];
    __shared__ float emb[832];
    __shared__ float red[32];
    __shared__ float wo_part[4][64];
    __shared__ float part[8][32];
    const int tile=blockIdx.x, b=blockIdx.y, t=threadIdx.x;

    mp_s[t]=g_maxpool[b*256+t];
    for (int i=t;i<768;i+=256) emb[i]=seq[(size_t)b*4096*768+i];
    __syncthreads();
    {
        int o=t&63, seg=t>>6;
        float a=0.f;
        #pragma unroll 8
        for (int k=seg*64;k<seg*64+64;k++) a=fmaf(mp_s[k],Wo[k*64+o],a);
        wo_part[seg][o]=a;
    }
    __syncthreads();
    if (t<64) emb[768+t]=wo_part[0][t]+wo_part[1][t]+wo_part[2][t]+wo_part[3][t]+bo[t];
    __syncthreads();
    float s=0.f;
    for (int i=t;i<832;i+=256) s+=emb[i];
    float mu=block_sum(s,red,t)*(1.0f/832.0f);
    float vs=0.f;
    for (int i=t;i<832;i+=256){ float d=emb[i]-mu; vs+=d*d; }
    float var=block_sum(vs,red,t)*(1.0f/832.0f);
    float inv_std=rsqrtf(var+1e-5f);
    for (int i=t;i<832;i+=256) emb[i]=(emb[i]-mu)*inv_std*ln_g[i]+ln_b[i];
    __syncthreads();
    {
        const int col=t&31, seg=t>>5, gcol=tile*32+col;
        const float* w=fc1_w+gcol;
        float a=0.f;
        const int k0=seg*104;
        #pragma unroll 8
        for (int k=k0;k<k0+104;k++) a=fmaf(emb[k],w[(size_t)k*512],a);
        part[seg][col]=a;
    }
    __syncthreads();
    if (t<32){
        float sum=part[0][t]+part[1][t]+part[2][t]+part[3][t]
                 +part[4][t]+part[5][t]+part[6][t]+part[7][t];
        int gc=tile*32+t;
        g_h1[b*512+gc]=gelu_exact(sum+fc1_b[gc]);
    }
}

__global__ __launch_bounds__(512)
void fc2_fc3_kernel(const float* __restrict__ fc2_w, const float* __restrict__ fc2_b,
                    const float* __restrict__ fc3_w, const float* __restrict__ fc3_b,
                    float* __restrict__ out)
{
    __shared__ float hs[512];
    __shared__ float part[2][200];
    __shared__ float h2[200];
    const int b=blockIdx.x, t=threadIdx.x;

    hs[t]=g_h1[b*512+t];
    __syncthreads();
    {
        int seg=t>>8, o=t&255;
        if (o<200){
            const float* w=fc2_w+(size_t)(seg*256)*200+o;
            const float* x=hs+seg*256;
            float a0=0.f, a1=0.f;
            #pragma unroll 8
            for (int k=0;k<256;k+=2){
                a0=fmaf(x[k],  w[(size_t)k*200],     a0);
                a1=fmaf(x[k+1],w[(size_t)(k+1)*200], a1);
            }
            part[seg][o]=a0+a1;
        }
    }
    __syncthreads();
    if (t<200) h2[t]=gelu_exact(part[0][t]+part[1][t]+fc2_b[t]);
    __syncthreads();
    if (t<64){
        int o=t>>5, lane=t&31;
        float a=0.f;
        #pragma unroll
        for (int k=lane;k<200;k+=32) a=fmaf(h2[k],fc3_w[k*2+o],a);
        #pragma unroll
        for (int off=16;off;off>>=1) a+=__shfl_xor_sync(0xffffffffu,a,off);
        if (lane==0) out[b*2+o]=a+fc3_b[o];
    }
}

// ---------------------------------------------------------------------------
extern "C" void kernel_launch(void* const* d_in, const int* in_sizes, int n_in,
                              void* d_out, int out_size)
{
    const float* seq   =(const float*)d_in[0];
    const float* node1 =(const float*)d_in[1];
    const float* node2 =(const float*)d_in[2];
    const float* Wq    =(const float*)d_in[3];
    const float* bq    =(const float*)d_in[4];
    const float* Wk    =(const float*)d_in[5];
    const float* bk    =(const float*)d_in[6];
    const float* Wv    =(const float*)d_in[7];
    const float* bv    =(const float*)d_in[8];
    const float* Wo    =(const float*)d_in[9];
    const float* bo    =(const float*)d_in[10];
    const float* ln_g  =(const float*)d_in[11];
    const float* ln_b  =(const float*)d_in[12];
    const float* fc1_w =(const float*)d_in[13];
    const float* fc1_b =(const float*)d_in[14];
    const float* fc2_w =(const float*)d_in[15];
    const float* fc2_b =(const float*)d_in[16];
    const float* fc3_w =(const float*)d_in[17];
    const float* fc3_b =(const float*)d_in[18];

    const size_t smem_bytes = (size_t)SMEMF * sizeof(float);
    cudaFuncSetAttribute(attn_mma_kernel,
                         cudaFuncAttributeMaxDynamicSharedMemorySize, (int)smem_bytes);

    attn_mma_kernel<<<dim3(NHEADS,32), 256, smem_bytes>>>(
        seq, node1, node2, Wq, bq, Wk, bk, Wv, bv);

    emb_ln_fc1_kernel<<<dim3(16,32), 256>>>(seq, Wo, bo, ln_g, ln_b, fc1_w, fc1_b);
    fc2_fc3_kernel<<<32, 512>>>(fc2_w, fc2_b, fc3_w, fc3_b, (float*)d_out);
}